// round 12
// baseline (speedup 1.0000x reference)
#include <cuda_runtime.h>
#include <cuda_bf16.h>
#include <cstddef>
#include <cstdint>

#define NNODES 50000
#define NPER   25000
#define NEDGE  600000
#define RREL   8
#define NB     4
#define INDIM  256
#define HID    128
#define OUTD2  64
#define NSEG   (NNODES * RREL)   // 400000
#define MAXD   96                // padded slots per dst
#define ROWS   64                // dst rows per fused block
#define NBLK   782               // ceil(50000/64)
#define CHUNKS 20                // 640 / 32
#define ACH    4096              // bytes per A chunk buffer (64 rows x 64B)
#define A_TOT  (CHUNKS * 2 * ACH)    // 163840

// ---------------- low-level helpers -----------------------------------------
__device__ __forceinline__ uint32_t smem_u32(const void* p) {
    uint32_t a;
    asm("{ .reg .u64 t; cvta.to.shared.u64 t, %1; cvt.u32.u64 %0, t; }"
        : "=r"(a) : "l"(p));
    return a;
}
__device__ __forceinline__ void cpasync16(uint32_t sdst, const void* gsrc) {
    asm volatile("{ .reg .u64 g; cvta.to.global.u64 g, %1;"
                 " cp.async.cg.shared.global [%0], [g], 16; }"
                 :: "r"(sdst), "l"(gsrc) : "memory");
}
__device__ __forceinline__ void cp_commit() {
    asm volatile("cp.async.commit_group;" ::: "memory");
}
template<int N>
__device__ __forceinline__ void cp_wait() {
    asm volatile("cp.async.wait_group %0;" :: "n"(N) : "memory");
}
__device__ __forceinline__ void ldmA(uint32_t* r, uint32_t addr) {
    asm volatile("ldmatrix.sync.aligned.m8n8.x4.shared.b16 {%0,%1,%2,%3}, [%4];"
        : "=r"(r[0]), "=r"(r[1]), "=r"(r[2]), "=r"(r[3]) : "r"(addr));
}
__device__ __forceinline__ void ldmBT(uint32_t* r, uint32_t addr) {
    asm volatile("ldmatrix.sync.aligned.m8n8.x4.trans.shared.b16 {%0,%1,%2,%3}, [%4];"
        : "=r"(r[0]), "=r"(r[1]), "=r"(r[2]), "=r"(r[3]) : "r"(addr));
}
__device__ __forceinline__ void mma16816(float* d, const uint32_t* a,
                                         const uint32_t* b) {
    asm volatile(
        "mma.sync.aligned.m16n8k16.row.col.f32.bf16.bf16.f32 "
        "{%0,%1,%2,%3}, {%4,%5,%6,%7}, {%8,%9}, {%0,%1,%2,%3};"
        : "+f"(d[0]), "+f"(d[1]), "+f"(d[2]), "+f"(d[3])
        : "r"(a[0]), "r"(a[1]), "r"(a[2]), "r"(a[3]), "r"(b[0]), "r"(b[1]));
}

// A-tile swizzle: row m (64B compact), byte-in-row s (16B-granule XOR).
// Row starts stay 16B-aligned (ldmatrix-legal); any 8-row ldmatrix phase at
// fixed s hits 16B-bank columns (4m + ((m>>1)&3)) mod 8 = permutation of 0..7.
__device__ __forceinline__ uint32_t aphys(int m, int s) {
    return (uint32_t)(m * 64 + (s ^ (((m >> 1) & 3) << 4)));
}

// ---------------- fast bf16 hi/lo split (cvt.rn.bf16x2) ----------------------
__device__ __forceinline__ uint32_t pack2(float lo, float hi) {
    uint32_t r;
    asm("cvt.rn.bf16x2.f32 %0, %1, %2;" : "=r"(r) : "f"(hi), "f"(lo));
    return r;
}
__device__ __forceinline__ void split4f(float4 v, uint32_t& h0, uint32_t& h1,
                                        uint32_t& l0, uint32_t& l1) {
    h0 = pack2(v.x, v.y);
    h1 = pack2(v.z, v.w);
    float hx = __uint_as_float(h0 << 16);
    float hy = __uint_as_float(h0 & 0xffff0000u);
    float hz = __uint_as_float(h1 << 16);
    float hw = __uint_as_float(h1 & 0xffff0000u);
    l0 = pack2(v.x - hx, v.y - hy);
    l1 = pack2(v.z - hz, v.w - hw);
}
__device__ __forceinline__ void split4u(float4 v, unsigned long long& H,
                                        unsigned long long& L) {
    uint32_t h0, h1, l0, l1;
    split4f(v, h0, h1, l0, l1);
    H = (unsigned long long)h0 | ((unsigned long long)h1 << 32);
    L = (unsigned long long)l0 | ((unsigned long long)l1 << 32);
}

// ---------------- scratch (device globals: no allocation allowed) ----------
__device__ int   g_cnt[NSEG];            // per-(dst,rel) counts
__device__ int   g_fill[NNODES];         // per-dst degree / slot cursor
__device__ int   g_eslots[(size_t)NNODES * MAXD];
__device__ float g_x2[(size_t)NNODES * HID];
__device__ int   g_is64;
// stacked weights [k=640][outd] bf16 hi/lo, row-major
__device__ unsigned long long g_wbh0[20480], g_wbl0[20480];
__device__ unsigned long long g_wbh1[20480], g_wbl1[20480];
__device__ unsigned long long g_wbh2[10240], g_wbl2[10240];

__device__ __forceinline__ int ld_idx(const void* p, long i) {
    return g_is64 ? (int)((const long long*)p)[i] : ((const int*)p)[i];
}

// ---------------- launch 1: zero + dtype detect + weight prep ---------------
__global__ void pre_kernel(const int* p,
                           const float* b0, const float* r0,
                           const float* b1, const float* r1,
                           const float* b2, const float* r2) {
    int i = blockIdx.x * blockDim.x + threadIdx.x;
    if (i == 0) {
        int any = 0;
        #pragma unroll 8
        for (int j = 1; j < 2048; j += 2) any |= p[j];
        g_is64 = (any == 0) ? 1 : 0;
    }
    if (i < NSEG) g_cnt[i] = 0;
    else if (i < NSEG + NNODES) g_fill[i - NSEG] = 0;

    if (i < 51200) {   // bf16 hi/lo weight conversion, 4 values per thread
        int conv = i < 20480 ? 0 : (i < 40960 ? 1 : 2);
        int u = i - (conv == 1 ? 20480 : (conv == 2 ? 40960 : 0));
        int outd = (conv == 2) ? OUTD2 : HID;
        const float* bases = conv == 0 ? b0 : (conv == 1 ? b1 : b2);
        const float* root  = conv == 0 ? r0 : (conv == 1 ? r1 : r2);
        unsigned long long* oh = conv == 0 ? g_wbh0 : (conv == 1 ? g_wbh1 : g_wbh2);
        unsigned long long* ol = conv == 0 ? g_wbl0 : (conv == 1 ? g_wbl1 : g_wbl2);
        int base = u * 4;
        int k = base / outd, o0 = base % outd;
        float4 v;
        float* vv = (float*)&v;
        #pragma unroll
        for (int j = 0; j < 4; j++)
            vv[j] = (k < 512) ? bases[(size_t)k * outd + o0 + j]
                              : root[(size_t)(k - 512) * outd + o0 + j];
        unsigned long long H, L;
        split4u(v, H, L);
        oh[u] = H; ol[u] = L;
    }
}

// ---------------- launch 2: scatter edges into padded slots + rel counts ----
__global__ void fill_kernel(const void* ei, const void* et) {
    int e = blockIdx.x * blockDim.x + threadIdx.x;
    if (e >= NEDGE) return;
    int src = ld_idx(ei, e);
    int dst = ld_idx(ei, (long)NEDGE + e);
    int t   = ld_idx(et, e);
    int pos = atomicAdd(&g_fill[dst], 1);
    if (pos < MAXD) g_eslots[(size_t)dst * MAXD + pos] = src * RREL + t;
    atomicAdd(&g_cnt[dst * RREL + t], 1);
}

// ---------------- launch 3: both input projections ---------------------------
#define NBLKP ((NPER + 63) / 64)
__global__ void __launch_bounds__(256)
proj_gemm2(const float* __restrict__ xp, const float* __restrict__ Wp,
           const float* __restrict__ bp,
           const float* __restrict__ xa, const float* __restrict__ Wa,
           const float* __restrict__ ba,
           float* __restrict__ o1, float* __restrict__ o2) {
    constexpr int BM = 64, BK = 16, ON = HID, TN = ON / 16;
    __shared__ __align__(16) float As[BK][BM];
    __shared__ __align__(16) float Bs[BK][ON];
    int half = blockIdx.x >= NBLKP;
    const float* xin  = half ? xa : xp;
    const float* W    = half ? Wa : Wp;
    const float* bias = half ? ba : bp;
    size_t obase = half ? (size_t)NPER * HID : 0;
    int bm = (blockIdx.x - (half ? NBLKP : 0)) * BM;
    int tid = threadIdx.x, tx = tid & 15, ty = tid >> 4;
    int arow = tid >> 2, asub = (tid & 3) * 4;
    int n = bm + arow;
    bool rowok = n < NPER;
    float acc[4][TN] = {};
    for (int k0 = 0; k0 < INDIM; k0 += BK) {
        float4 v = make_float4(0.f, 0.f, 0.f, 0.f);
        if (rowok) v = *(const float4*)(xin + (size_t)n * INDIM + k0 + asub);
        As[asub + 0][arow] = v.x; As[asub + 1][arow] = v.y;
        As[asub + 2][arow] = v.z; As[asub + 3][arow] = v.w;
        const float* bsrc = W + (size_t)k0 * ON;
        #pragma unroll
        for (int i = tid * 4; i < BK * ON; i += 1024)
            *(float4*)((float*)Bs + i) = *(const float4*)(bsrc + i);
        __syncthreads();
        #pragma unroll
        for (int k = 0; k < BK; k++) {
            float4 a4 = *(float4*)&As[k][ty * 4];
            float av[4] = {a4.x, a4.y, a4.z, a4.w};
            float bv[TN];
            #pragma unroll
            for (int j = 0; j < TN; j += 4) {
                float4 b4 = *(float4*)&Bs[k][tx * TN + j];
                bv[j] = b4.x; bv[j + 1] = b4.y; bv[j + 2] = b4.z; bv[j + 3] = b4.w;
            }
            #pragma unroll
            for (int i = 0; i < 4; i++)
                #pragma unroll
                for (int j = 0; j < TN; j++)
                    acc[i][j] = fmaf(av[i], bv[j], acc[i][j]);
        }
        __syncthreads();
    }
    #pragma unroll
    for (int i = 0; i < 4; i++) {
        int m = bm + ty * 4 + i;
        if (m >= NPER) break;
        #pragma unroll
        for (int j = 0; j < TN; j++) {
            int o = tx * TN + j;
            float v = fmaxf(acc[i][j] + bias[o], 0.f);
            o1[obase + (size_t)m * HID + o] = v;
            o2[obase + (size_t)m * HID + o] = v;
        }
    }
}

// ---------------- fused conv: agg into smem A tiles, then HMMA ---------------
// Per block: 64 dst rows. Phase 1: 8 warps x 8 rows gather/accumulate, bf16
// hi/lo split straight into swizzled smem chunk tiles. Phase 2: 20-chunk HMMA
// mainloop (warps = 4m x 2n), B double-buffered from global (L2-resident).
// D = Ah@Bh + Al@Bh + Ah@Bl. MODE 0: relu | 1: relu+resid | 2: plain.
template<int OUTD, int MODE, int XIN2, int YOUT2, int CONV>
__global__ void __launch_bounds__(256)
fused_conv(const float* __restrict__ xg,
           const float* __restrict__ comp,
           const float* __restrict__ bias,
           const float* __restrict__ resid,
           float* __restrict__ yg) {
    constexpr int NHALF = OUTD / 2;
    constexpr int NT  = OUTD / 16;       // n-tiles (8 cols) per warp
    constexpr int BST = OUTD + 8;        // B smem row stride (bf16), 16B-mult
    constexpr int BHB = 32 * BST * 2;    // bytes per B hi (or lo) buffer
    constexpr int BSEG = 32 * OUTD / 8;  // 16B segs per B half-chunk
    constexpr int B_OFF = A_TOT;
    constexpr int NRM_OFF = B_OFF + 4 * BHB;
    constexpr int CMP_OFF = NRM_OFF + ROWS * RREL * 4;
    extern __shared__ char sm[];
    uint32_t smb = smem_u32(sm);
    float* nrm_s  = (float*)(sm + NRM_OFF);
    float* comp_s = (float*)(sm + CMP_OFF);
    int tid = threadIdx.x, lane = tid & 31, w = tid >> 5;
    int n0 = blockIdx.x * ROWS;
    const float* x = XIN2 ? (const float*)g_x2 : xg;
    float* y = YOUT2 ? (float*)g_x2 : yg;
    const unsigned long long* wbh =
        CONV == 0 ? g_wbh0 : (CONV == 1 ? g_wbh1 : g_wbh2);
    const unsigned long long* wbl =
        CONV == 0 ? g_wbl0 : (CONV == 1 ? g_wbl1 : g_wbl2);

    // ---- B staging (cp.async) ----
    auto stageB = [&](int c, int buf) {
        uint32_t boff = smb + B_OFF + buf * (2 * BHB);
        #pragma unroll
        for (int i = 0; i < (BSEG + 255) / 256; i++) {
            int o = tid + i * 256;
            if (BSEG % 256 && o >= BSEG) break;
            int r = o / (OUTD / 8), s = o % (OUTD / 8);
            size_t g = ((size_t)(c * 32 + r) * OUTD + s * 8) * 2;
            uint32_t d = boff + (r * BST + s * 8) * 2;
            cpasync16(d, (const char*)wbh + g);
            cpasync16(d + BHB, (const char*)wbl + g);
        }
    };
    stageB(0, 0);          // overlaps with aggregation phase
    cp_commit();

    // ---- prologue tables ----
    if (tid < 32) comp_s[tid] = comp[tid];
    for (int i = tid; i < ROWS * RREL; i += 256) {
        int n = n0 + (i >> 3);
        float c = (n < NNODES) ? (float)g_cnt[n * RREL + (i & 7)] : 1.0f;
        nrm_s[i] = 1.0f / fmaxf(c, 1.0f);
    }
    __syncthreads();

    // ---- phase 1: aggregation -> swizzled smem A chunk tiles ----
    // row m, plane p: chunk = p*4 + (lane>>3); byte-in-row s = (lane&7)*8
    auto a_store = [&](int m, int p, uint32_t h0, uint32_t h1,
                       uint32_t l0, uint32_t l1) {
        int c = p * 4 + (lane >> 3);
        uint32_t ph = aphys(m, (lane & 7) * 8);
        *(uint2*)(sm + (uint32_t)(c * 2 + 0) * ACH + ph) = make_uint2(h0, h1);
        *(uint2*)(sm + (uint32_t)(c * 2 + 1) * ACH + ph) = make_uint2(l0, l1);
    };
    #pragma unroll
    for (int pp = 0; pp < 4; pp++) {
        int mA = w * 8 + pp * 2, mB = mA + 1;
        int nA = n0 + mA, nB = n0 + mB;
        float4 z4 = make_float4(0.f, 0.f, 0.f, 0.f);
        {   // x[dst] plane (plane 4)
            float4 xa = (nA < NNODES)
                ? *(const float4*)(x + (size_t)nA * HID + lane * 4) : z4;
            float4 xb = (nB < NNODES)
                ? *(const float4*)(x + (size_t)nB * HID + lane * 4) : z4;
            uint32_t h0, h1, l0, l1;
            split4f(xa, h0, h1, l0, l1);
            a_store(mA, 4, h0, h1, l0, l1);
            split4f(xb, h0, h1, l0, l1);
            a_store(mB, 4, h0, h1, l0, l1);
        }
        int endA = 0, endB = 0;
        size_t sA = (size_t)nA * MAXD, sB = (size_t)nB * MAXD;
        if (nA < NNODES) endA = min(g_fill[nA], MAXD);
        if (nB < NNODES) endB = min(g_fill[nB], MAXD);

        float4 aA[4] = {z4, z4, z4, z4};
        float4 aB[4] = {z4, z4, z4, z4};
        int eA = 0, eB = 0;
        int cA = (eA < endA) ? g_eslots[sA] : 0;
        int cB = (eB < endB) ? g_eslots[sB] : 0;
        while (eA < endA || eB < endB) {
            bool dA = eA < endA, dB = eB < endB;
            float4 vA = *((const float4*)(x + (size_t)(cA >> 3) * HID) + lane);
            float4 vB = *((const float4*)(x + (size_t)(cB >> 3) * HID) + lane);
            int cA2 = (eA + 1 < endA) ? g_eslots[sA + eA + 1] : 0;
            int cB2 = (eB + 1 < endB) ? g_eslots[sB + eB + 1] : 0;
            int etA = cA & 7, etB = cB & 7;
            float kA = dA ? nrm_s[(mA << 3) | etA] : 0.f;
            float kB = dB ? nrm_s[(mB << 3) | etB] : 0.f;
            #pragma unroll
            for (int b = 0; b < 4; b++) {
                float ca = kA * comp_s[etA * 4 + b];
                float cb = kB * comp_s[etB * 4 + b];
                aA[b].x = fmaf(ca, vA.x, aA[b].x);
                aA[b].y = fmaf(ca, vA.y, aA[b].y);
                aA[b].z = fmaf(ca, vA.z, aA[b].z);
                aA[b].w = fmaf(ca, vA.w, aA[b].w);
                aB[b].x = fmaf(cb, vB.x, aB[b].x);
                aB[b].y = fmaf(cb, vB.y, aB[b].y);
                aB[b].z = fmaf(cb, vB.z, aB[b].z);
                aB[b].w = fmaf(cb, vB.w, aB[b].w);
            }
            eA += dA; eB += dB;
            if (dA) cA = cA2;
            if (dB) cB = cB2;
        }
        #pragma unroll
        for (int b = 0; b < 4; b++) {
            uint32_t h0, h1, l0, l1;
            split4f(aA[b], h0, h1, l0, l1);
            a_store(mA, b, h0, h1, l0, l1);
            split4f(aB[b], h0, h1, l0, l1);
            a_store(mB, b, h0, h1, l0, l1);
        }
    }
    __syncthreads();

    // ---- phase 2: HMMA mainloop over 20 chunks ----
    int mp = w & 3, nh = w >> 2;
    float acc[NT][4] = {};
    for (int c = 0; c < CHUNKS; c++) {
        if (c + 1 < CHUNKS) {
            stageB(c + 1, (c + 1) & 1);
            cp_commit();
            cp_wait<1>();
        } else {
            cp_wait<0>();
        }
        __syncthreads();
        uint32_t ahi = smb + (uint32_t)(c * 2 + 0) * ACH;
        uint32_t alo = smb + (uint32_t)(c * 2 + 1) * ACH;
        uint32_t boff = smb + B_OFF + (c & 1) * (2 * BHB);
        #pragma unroll
        for (int kk = 0; kk < 32; kk += 16) {
            int am = mp * 16 + (lane & 15);
            uint32_t ad = aphys(am, kk * 2 + (lane >> 4) * 16);
            uint32_t ah[4], al[4];
            ldmA(ah, ahi + ad);
            ldmA(al, alo + ad);
            uint32_t bh[2 * NT], bl[2 * NT];
            #pragma unroll
            for (int jp = 0; jp < NT / 2; jp++) {
                uint32_t bd = boff
                    + ((kk + (lane & 15)) * BST
                       + nh * NHALF + jp * 16 + (lane >> 4) * 8) * 2;
                ldmBT(bh + jp * 4, bd);
                ldmBT(bl + jp * 4, bd + BHB);
            }
            #pragma unroll
            for (int j = 0; j < NT; j++) {
                mma16816(acc[j], ah, bh + j * 2);
                mma16816(acc[j], al, bh + j * 2);
                mma16816(acc[j], ah, bl + j * 2);
            }
        }
        __syncthreads();
    }

    // ---- epilogue ----
    int r0 = n0 + mp * 16 + (lane >> 2);
    int r1 = r0 + 8;
    #pragma unroll
    for (int j = 0; j < NT; j++) {
        int col = nh * NHALF + j * 8 + (lane & 3) * 2;
        float2 bb = *(const float2*)(bias + col);
        float2 v0 = make_float2(acc[j][0] + bb.x, acc[j][1] + bb.y);
        float2 v1 = make_float2(acc[j][2] + bb.x, acc[j][3] + bb.y);
        if (MODE == 0) {
            v0.x = fmaxf(v0.x, 0.f); v0.y = fmaxf(v0.y, 0.f);
            v1.x = fmaxf(v1.x, 0.f); v1.y = fmaxf(v1.y, 0.f);
        } else if (MODE == 1) {
            if (r0 < NNODES) {
                float2 rr = *(const float2*)(resid + (size_t)r0 * OUTD + col);
                v0.x = fmaxf(v0.x, 0.f) + rr.x;
                v0.y = fmaxf(v0.y, 0.f) + rr.y;
            }
            if (r1 < NNODES) {
                float2 rr = *(const float2*)(resid + (size_t)r1 * OUTD + col);
                v1.x = fmaxf(v1.x, 0.f) + rr.x;
                v1.y = fmaxf(v1.y, 0.f) + rr.y;
            }
        }
        if (r0 < NNODES) *(float2*)(y + (size_t)r0 * OUTD + col) = v0;
        if (r1 < NNODES) *(float2*)(y + (size_t)r1 * OUTD + col) = v1;
    }
}

// ---------------- launch ----------------------------------------------------
extern "C" void kernel_launch(void* const* d_in, const int* in_sizes, int n_in,
                              void* d_out, int out_size) {
    const float* x_paper  = (const float*)d_in[0];
    const float* x_author = (const float*)d_in[1];
    const float* W_paper  = (const float*)d_in[2];
    const float* b_paper  = (const float*)d_in[3];
    const float* W_author = (const float*)d_in[4];
    const float* b_author = (const float*)d_in[5];
    const float* bases0 = (const float*)d_in[6];
    const float* comp0  = (const float*)d_in[7];
    const float* root0  = (const float*)d_in[8];
    const float* bias0  = (const float*)d_in[9];
    const float* bases1 = (const float*)d_in[10];
    const float* comp1  = (const float*)d_in[11];
    const float* root1  = (const float*)d_in[12];
    const float* bias1  = (const float*)d_in[13];
    const float* bases2 = (const float*)d_in[14];
    const float* comp2  = (const float*)d_in[15];
    const float* root2  = (const float*)d_in[16];
    const float* bias2  = (const float*)d_in[17];
    const void*  edge_index = d_in[18];
    const void*  edge_type  = d_in[19];

    // output pytree flat order: out [N,64], x_init, x_init, h0 (each [N,128])
    float* out0 = (float*)d_out;
    float* lat0 = out0 + (size_t)NNODES * OUTD2;
    float* lat1 = lat0 + (size_t)NNODES * HID;
    float* lat2 = lat1 + (size_t)NNODES * HID;

    const int T = 256;
    const int gpre  = (NSEG + NNODES + T - 1) / T;
    const int gedge = (NEDGE + T - 1) / T;

    // dynamic smem: A tiles + B dbuf + nrm + comp
    const int smemA = A_TOT + 4 * (32 * (HID + 8) * 2)   + ROWS * RREL * 4 + 128;
    const int smemB = A_TOT + 4 * (32 * (OUTD2 + 8) * 2) + ROWS * RREL * 4 + 128;

    cudaFuncSetAttribute(fused_conv<HID,   0, 0, 0, 0>,
                         cudaFuncAttributeMaxDynamicSharedMemorySize, smemA);
    cudaFuncSetAttribute(fused_conv<HID,   1, 0, 1, 1>,
                         cudaFuncAttributeMaxDynamicSharedMemorySize, smemA);
    cudaFuncSetAttribute(fused_conv<OUTD2, 2, 1, 0, 2>,
                         cudaFuncAttributeMaxDynamicSharedMemorySize, smemB);

    // 1: zero + dtype + weight bf16 prep
    pre_kernel<<<gpre, T>>>((const int*)edge_index,
                            bases0, root0, bases1, root1, bases2, root2);
    // 2: padded-slot scatter + rel counts
    fill_kernel<<<gedge, T>>>(edge_index, edge_type);
    // 3: input projections -> x_init into both latent slots
    proj_gemm2<<<2 * NBLKP, T>>>(x_paper, W_paper, b_paper,
                                 x_author, W_author, b_author, lat0, lat1);

    // 4: fused conv0: x = x_init -> h0 = relu(.) -> lat2   [ncu target]
    fused_conv<HID, 0, 0, 0, 0><<<NBLK, T, smemA>>>(
        lat0, comp0, bias0, nullptr, lat2);
    // 5: fused conv1: x = h0 -> x2 = h0 + relu(.) -> g_x2
    fused_conv<HID, 1, 0, 1, 1><<<NBLK, T, smemA>>>(
        lat2, comp1, bias1, lat2, nullptr);
    // 6: fused conv2: x = g_x2 -> out (no relu) -> out0
    fused_conv<OUTD2, 2, 1, 0, 2><<<NBLK, T, smemB>>>(
        nullptr, comp2, bias2, nullptr, out0);
}

// round 13
// speedup vs baseline: 1.7777x; 1.7777x over previous
#include <cuda_runtime.h>
#include <cuda_bf16.h>
#include <cstddef>
#include <cstdint>

#define NNODES 50000
#define NPER   25000
#define NEDGE  600000
#define RREL   8
#define NB     4
#define INDIM  256
#define HID    128
#define OUTD2  64
#define NSEG   (NNODES * RREL)   // 400000
#define NTILE  391               // ceil(50000/128)
#define MAXD   96                // padded slots per dst
#define CHUNKS 20                // 640 / 32
#define AST    40                // A smem row stride in mma_conv (bf16)
#define ABUF   10240             // 128*40*2 bytes, one A hi or lo buffer
#define ABLK   20480             // per double-buffer step (hi+lo)
#define NPB    391               // proj blocks per node type (ceil 25000/64)
#define PCH    8                 // proj K chunks (256/32)
#define APTOT  (PCH * 2 * 4096)  // proj A smem: 65536

// ---------------- low-level helpers -----------------------------------------
__device__ __forceinline__ uint32_t smem_u32(const void* p) {
    uint32_t a;
    asm("{ .reg .u64 t; cvta.to.shared.u64 t, %1; cvt.u32.u64 %0, t; }"
        : "=r"(a) : "l"(p));
    return a;
}
__device__ __forceinline__ void cpasync16(uint32_t sdst, const void* gsrc) {
    asm volatile("{ .reg .u64 g; cvta.to.global.u64 g, %1;"
                 " cp.async.cg.shared.global [%0], [g], 16; }"
                 :: "r"(sdst), "l"(gsrc) : "memory");
}
__device__ __forceinline__ void cp_commit() {
    asm volatile("cp.async.commit_group;" ::: "memory");
}
template<int N>
__device__ __forceinline__ void cp_wait() {
    asm volatile("cp.async.wait_group %0;" :: "n"(N) : "memory");
}
__device__ __forceinline__ void ldmA(uint32_t* r, uint32_t addr) {
    asm volatile("ldmatrix.sync.aligned.m8n8.x4.shared.b16 {%0,%1,%2,%3}, [%4];"
        : "=r"(r[0]), "=r"(r[1]), "=r"(r[2]), "=r"(r[3]) : "r"(addr));
}
__device__ __forceinline__ void ldmBT(uint32_t* r, uint32_t addr) {
    asm volatile("ldmatrix.sync.aligned.m8n8.x4.trans.shared.b16 {%0,%1,%2,%3}, [%4];"
        : "=r"(r[0]), "=r"(r[1]), "=r"(r[2]), "=r"(r[3]) : "r"(addr));
}
__device__ __forceinline__ void mma16816(float* d, const uint32_t* a,
                                         const uint32_t* b) {
    asm volatile(
        "mma.sync.aligned.m16n8k16.row.col.f32.bf16.bf16.f32 "
        "{%0,%1,%2,%3}, {%4,%5,%6,%7}, {%8,%9}, {%0,%1,%2,%3};"
        : "+f"(d[0]), "+f"(d[1]), "+f"(d[2]), "+f"(d[3])
        : "r"(a[0]), "r"(a[1]), "r"(a[2]), "r"(a[3]), "r"(b[0]), "r"(b[1]));
}

// Compact A-tile swizzle (validated in R12 run): row m at 64B, 16B-granule XOR.
__device__ __forceinline__ uint32_t aphys(int m, int s) {
    return (uint32_t)(m * 64 + (s ^ (((m >> 1) & 3) << 4)));
}

// ---------------- fast bf16 hi/lo split (cvt.rn.bf16x2) ----------------------
__device__ __forceinline__ uint32_t pack2(float lo, float hi) {
    uint32_t r;
    asm("cvt.rn.bf16x2.f32 %0, %1, %2;" : "=r"(r) : "f"(hi), "f"(lo));
    return r;
}
__device__ __forceinline__ void split4f(float4 v, uint32_t& h0, uint32_t& h1,
                                        uint32_t& l0, uint32_t& l1) {
    h0 = pack2(v.x, v.y);
    h1 = pack2(v.z, v.w);
    float hx = __uint_as_float(h0 << 16);
    float hy = __uint_as_float(h0 & 0xffff0000u);
    float hz = __uint_as_float(h1 << 16);
    float hw = __uint_as_float(h1 & 0xffff0000u);
    l0 = pack2(v.x - hx, v.y - hy);
    l1 = pack2(v.z - hz, v.w - hw);
}
__device__ __forceinline__ void split4u(float4 v, unsigned long long& H,
                                        unsigned long long& L) {
    uint32_t h0, h1, l0, l1;
    split4f(v, h0, h1, l0, l1);
    H = (unsigned long long)h0 | ((unsigned long long)h1 << 32);
    L = (unsigned long long)l0 | ((unsigned long long)l1 << 32);
}

// ---------------- scratch (device globals: no allocation allowed) ----------
__device__ int   g_cnt[NSEG];
__device__ int   g_fill[NNODES];
__device__ int   g_eslots[(size_t)NNODES * MAXD];
__device__ float g_x2[(size_t)NNODES * HID];
__device__ int   g_is64;
// aggregated A bf16 hi/lo in MMA chunk layout: [tile][chunk(20)][row(128)][k(32)]
__device__ unsigned long long g_abh[(size_t)NTILE * CHUNKS * 1024];
__device__ unsigned long long g_abl[(size_t)NTILE * CHUNKS * 1024];
// stacked conv weights [k=640][outd] bf16 hi/lo
__device__ unsigned long long g_wbh0[20480], g_wbl0[20480];
__device__ unsigned long long g_wbh1[20480], g_wbl1[20480];
__device__ unsigned long long g_wbh2[10240], g_wbl2[10240];
// proj weights [k=256][128] bf16 hi/lo, per node type
__device__ unsigned long long g_wpph[8192], g_wppl[8192];
__device__ unsigned long long g_wpah[8192], g_wpal[8192];

__device__ __forceinline__ int ld_idx(const void* p, long i) {
    return g_is64 ? (int)((const long long*)p)[i] : ((const int*)p)[i];
}

// ---------------- launch 1: zero + dtype detect + all weight prep -----------
__global__ void pre_kernel(const int* p,
                           const float* b0, const float* r0,
                           const float* b1, const float* r1,
                           const float* b2, const float* r2,
                           const float* Wp, const float* Wa) {
    int i = blockIdx.x * blockDim.x + threadIdx.x;
    if (i == 0) {
        int any = 0;
        #pragma unroll 8
        for (int j = 1; j < 2048; j += 2) any |= p[j];
        g_is64 = (any == 0) ? 1 : 0;
    }
    if (i < NSEG) g_cnt[i] = 0;
    else if (i < NSEG + NNODES) g_fill[i - NSEG] = 0;

    if (i < 51200) {   // conv weights: 4 bf16 hi/lo values per thread
        int conv = i < 20480 ? 0 : (i < 40960 ? 1 : 2);
        int u = i - (conv == 1 ? 20480 : (conv == 2 ? 40960 : 0));
        int outd = (conv == 2) ? OUTD2 : HID;
        const float* bases = conv == 0 ? b0 : (conv == 1 ? b1 : b2);
        const float* root  = conv == 0 ? r0 : (conv == 1 ? r1 : r2);
        unsigned long long* oh = conv == 0 ? g_wbh0 : (conv == 1 ? g_wbh1 : g_wbh2);
        unsigned long long* ol = conv == 0 ? g_wbl0 : (conv == 1 ? g_wbl1 : g_wbl2);
        int base = u * 4;
        int k = base / outd, o0 = base % outd;
        float4 v;
        float* vv = (float*)&v;
        #pragma unroll
        for (int j = 0; j < 4; j++)
            vv[j] = (k < 512) ? bases[(size_t)k * outd + o0 + j]
                              : root[(size_t)(k - 512) * outd + o0 + j];
        unsigned long long H, L;
        split4u(v, H, L);
        oh[u] = H; ol[u] = L;
    } else if (i < 67584) {  // proj weights
        int u = i - 51200;
        int typ = u >= 8192;
        int uu = u & 8191;
        const float* W = typ ? Wa : Wp;
        unsigned long long* oh = typ ? g_wpah : g_wpph;
        unsigned long long* ol = typ ? g_wpal : g_wppl;
        float4 v = *(const float4*)(W + (size_t)uu * 4);
        unsigned long long H, L;
        split4u(v, H, L);
        oh[uu] = H; ol[uu] = L;
    }
}

// ---------------- launch 2: scatter edges into padded slots + rel counts ----
__global__ void fill_kernel(const void* ei, const void* et) {
    int e = blockIdx.x * blockDim.x + threadIdx.x;
    if (e >= NEDGE) return;
    int src = ld_idx(ei, e);
    int dst = ld_idx(ei, (long)NEDGE + e);
    int t   = ld_idx(et, e);
    int pos = atomicAdd(&g_fill[dst], 1);
    if (pos < MAXD) g_eslots[(size_t)dst * MAXD + pos] = src * RREL + t;
    atomicAdd(&g_cnt[dst * RREL + t], 1);
}

// ---------------- launch 3: HMMA input projection (both node types) ---------
// Per block 64 rows. Phase 1: x fp32 -> bf16 hi/lo smem chunk tiles (aphys
// swizzle). Phase 2: 8-chunk HMMA vs W hi/lo (B double-buffered). relu(x@W+b)
// written to BOTH latent slots. Blocks [0,391)=paper, [391,782)=author.
__global__ void __launch_bounds__(256)
proj_conv(const float* __restrict__ xp, const float* __restrict__ xa,
          const float* __restrict__ bp, const float* __restrict__ ba,
          float* __restrict__ o1, float* __restrict__ o2) {
    constexpr int OUTD = HID;
    constexpr int NT = 8, NHALF = 64;
    constexpr int BST = OUTD + 8;
    constexpr int BHB = 32 * BST * 2;
    constexpr int B_OFF = APTOT;
    extern __shared__ char sm[];
    uint32_t smb = smem_u32(sm);
    int tid = threadIdx.x, lane = tid & 31, w = tid >> 5;
    int half = blockIdx.x >= NPB;
    int blk = blockIdx.x - (half ? NPB : 0);
    int n0 = blk * 64;
    const float* x = half ? xa : xp;
    const float* bias = half ? ba : bp;
    const unsigned long long* wbh = half ? g_wpah : g_wpph;
    const unsigned long long* wbl = half ? g_wpal : g_wppl;

    auto stageB = [&](int c, int buf) {
        uint32_t boff = smb + B_OFF + buf * (2 * BHB);
        #pragma unroll
        for (int i = 0; i < 2; i++) {
            int o = tid + i * 256;           // 512 16B segs
            int r = o >> 4, s = o & 15;
            size_t g = ((size_t)(c * 32 + r) * OUTD + s * 8) * 2;
            uint32_t d = boff + (r * BST + s * 8) * 2;
            cpasync16(d, (const char*)wbh + g);
            cpasync16(d + BHB, (const char*)wbl + g);
        }
    };
    stageB(0, 0);
    cp_commit();

    // phase 1: convert x rows into smem hi/lo chunk tiles
    #pragma unroll
    for (int i = 0; i < 8; i++) {
        int m = w * 8 + i;
        int n = n0 + m;
        bool ok = n < NPER;
        #pragma unroll
        for (int h = 0; h < 2; h++) {
            float4 v = make_float4(0.f, 0.f, 0.f, 0.f);
            if (ok) v = *(const float4*)(x + (size_t)n * INDIM + h * 128 + lane * 4);
            uint32_t h0, h1, l0, l1;
            split4f(v, h0, h1, l0, l1);
            int c = h * 4 + (lane >> 3);
            uint32_t ph = aphys(m, (lane & 7) * 8);
            *(uint2*)(sm + (uint32_t)(c * 2 + 0) * 4096 + ph) = make_uint2(h0, h1);
            *(uint2*)(sm + (uint32_t)(c * 2 + 1) * 4096 + ph) = make_uint2(l0, l1);
        }
    }
    __syncthreads();

    // phase 2: 8-chunk HMMA mainloop
    int mp = w & 3, nh = w >> 2;
    float acc[NT][4] = {};
    for (int c = 0; c < PCH; c++) {
        if (c + 1 < PCH) {
            stageB(c + 1, (c + 1) & 1);
            cp_commit();
            cp_wait<1>();
        } else {
            cp_wait<0>();
        }
        __syncthreads();
        uint32_t ahi = smb + (uint32_t)(c * 2 + 0) * 4096;
        uint32_t alo = smb + (uint32_t)(c * 2 + 1) * 4096;
        uint32_t boff = smb + B_OFF + (c & 1) * (2 * BHB);
        #pragma unroll
        for (int kk = 0; kk < 32; kk += 16) {
            int am = mp * 16 + (lane & 15);
            uint32_t ad = aphys(am, kk * 2 + (lane >> 4) * 16);
            uint32_t ah[4], al[4];
            ldmA(ah, ahi + ad);
            ldmA(al, alo + ad);
            uint32_t bh[2 * NT], bl[2 * NT];
            #pragma unroll
            for (int jp = 0; jp < NT / 2; jp++) {
                uint32_t bd = boff
                    + ((kk + (lane & 15)) * BST
                       + nh * NHALF + jp * 16 + (lane >> 4) * 8) * 2;
                ldmBT(bh + jp * 4, bd);
                ldmBT(bl + jp * 4, bd + BHB);
            }
            #pragma unroll
            for (int j = 0; j < NT; j++) {
                mma16816(acc[j], ah, bh + j * 2);
                mma16816(acc[j], al, bh + j * 2);
                mma16816(acc[j], ah, bl + j * 2);
            }
        }
        __syncthreads();
    }

    // epilogue: relu(acc + bias) -> both latent slots
    int r0 = n0 + mp * 16 + (lane >> 2);
    int r1 = r0 + 8;
    size_t gb = (size_t)(half ? NPER : 0) * HID;
    #pragma unroll
    for (int j = 0; j < NT; j++) {
        int col = nh * NHALF + j * 8 + (lane & 3) * 2;
        float2 bb = *(const float2*)(bias + col);
        float2 v0 = make_float2(fmaxf(acc[j][0] + bb.x, 0.f),
                                fmaxf(acc[j][1] + bb.y, 0.f));
        float2 v1 = make_float2(fmaxf(acc[j][2] + bb.x, 0.f),
                                fmaxf(acc[j][3] + bb.y, 0.f));
        if (r0 < NPER) {
            *(float2*)(o1 + gb + (size_t)r0 * HID + col) = v0;
            *(float2*)(o2 + gb + (size_t)r0 * HID + col) = v0;
        }
        if (r1 < NPER) {
            *(float2*)(o1 + gb + (size_t)r1 * HID + col) = v1;
            *(float2*)(o2 + gb + (size_t)r1 * HID + col) = v1;
        }
    }
}

// ---------------- agg: slot gather -> bf16 hi/lo A in chunk layout ----------
template<int XIN2>
__global__ void __launch_bounds__(256)
agg_kernel(const float* __restrict__ xg, const float* __restrict__ comp) {
    __shared__ float comp_s[32];
    __shared__ float nrm_s[256];
    const float* x = XIN2 ? (const float*)g_x2 : xg;
    int tid = threadIdx.x;
    int n0 = blockIdx.x * 32;
    if (tid < 32) comp_s[tid] = comp[tid];
    {
        int n = n0 + (tid >> 3);
        float c = (n < NNODES) ? (float)g_cnt[n * RREL + (tid & 7)] : 1.0f;
        nrm_s[tid] = 1.0f / fmaxf(c, 1.0f);
    }
    __syncthreads();

    int lane = tid & 31, w = tid >> 5;
    auto aidx = [&](int n, int p) -> size_t {
        int c = p * 4 + (lane >> 3);
        return ((size_t)(n >> 7) * CHUNKS + c) * 1024 + (n & 127) * 8 + (lane & 7);
    };
    #pragma unroll
    for (int pp = 0; pp < 2; pp++) {
        int mA = w * 4 + pp * 2, mB = mA + 1;
        int nA = n0 + mA, nB = n0 + mB;
        float4 z4 = make_float4(0.f, 0.f, 0.f, 0.f);
        {
            float4 xav = (nA < NNODES)
                ? *(const float4*)(x + (size_t)nA * HID + lane * 4) : z4;
            float4 xbv = (nB < NNODES)
                ? *(const float4*)(x + (size_t)nB * HID + lane * 4) : z4;
            unsigned long long H, L;
            split4u(xav, H, L); g_abh[aidx(nA, 4)] = H; g_abl[aidx(nA, 4)] = L;
            split4u(xbv, H, L); g_abh[aidx(nB, 4)] = H; g_abl[aidx(nB, 4)] = L;
        }
        int endA = 0, endB = 0;
        size_t sA = (size_t)nA * MAXD, sB = (size_t)nB * MAXD;
        if (nA < NNODES) endA = min(g_fill[nA], MAXD);
        if (nB < NNODES) endB = min(g_fill[nB], MAXD);

        float4 aA[4] = {z4, z4, z4, z4};
        float4 aB[4] = {z4, z4, z4, z4};
        int eA = 0, eB = 0;
        int cA = (eA < endA) ? g_eslots[sA] : 0;
        int cB = (eB < endB) ? g_eslots[sB] : 0;
        while (eA < endA || eB < endB) {
            bool dA = eA < endA, dB = eB < endB;
            float4 vA = *((const float4*)(x + (size_t)(cA >> 3) * HID) + lane);
            float4 vB = *((const float4*)(x + (size_t)(cB >> 3) * HID) + lane);
            int cA2 = (eA + 1 < endA) ? g_eslots[sA + eA + 1] : 0;
            int cB2 = (eB + 1 < endB) ? g_eslots[sB + eB + 1] : 0;
            int etA = cA & 7, etB = cB & 7;
            float kA = dA ? nrm_s[(mA << 3) | etA] : 0.f;
            float kB = dB ? nrm_s[(mB << 3) | etB] : 0.f;
            #pragma unroll
            for (int b = 0; b < 4; b++) {
                float ca = kA * comp_s[etA * 4 + b];
                float cb = kB * comp_s[etB * 4 + b];
                aA[b].x = fmaf(ca, vA.x, aA[b].x);
                aA[b].y = fmaf(ca, vA.y, aA[b].y);
                aA[b].z = fmaf(ca, vA.z, aA[b].z);
                aA[b].w = fmaf(ca, vA.w, aA[b].w);
                aB[b].x = fmaf(cb, vB.x, aB[b].x);
                aB[b].y = fmaf(cb, vB.y, aB[b].y);
                aB[b].z = fmaf(cb, vB.z, aB[b].z);
                aB[b].w = fmaf(cb, vB.w, aB[b].w);
            }
            eA += dA; eB += dB;
            if (dA) cA = cA2;
            if (dB) cB = cB2;
        }
        #pragma unroll
        for (int b = 0; b < 4; b++) {
            unsigned long long H, L;
            split4u(aA[b], H, L); g_abh[aidx(nA, b)] = H; g_abl[aidx(nA, b)] = L;
            split4u(aB[b], H, L); g_abh[aidx(nB, b)] = H; g_abl[aidx(nB, b)] = L;
        }
    }
}

// ---------------- HMMA conv: D = Ah@Bh + Al@Bh + Ah@Bl ----------------------
// Per block: 128 rows x OUTD. K=640 in 20 chunks of 32, cp.async double-buffer,
// 2 blocks/SM. Weights selected by CONV inside device code.
template<int OUTD, int MODE, int YOUT2, int CONV>
__global__ void __launch_bounds__(256)
mma_conv(const float* __restrict__ bias,
         const float* __restrict__ resid,
         float* __restrict__ yg) {
    constexpr int NT = OUTD / 16;
    constexpr int NHALF = OUTD / 2;
    constexpr int BST = OUTD + 8;
    constexpr int BB  = 32 * BST * 2;
    constexpr int BSEG = 32 * OUTD / 8;
    extern __shared__ char smdyn[];
    uint32_t smb = smem_u32(smdyn);
    int tid = threadIdx.x, lane = tid & 31, w = tid >> 5;
    int mp = w & 3, nh = w >> 2;
    int tile = blockIdx.x;
    float* y = YOUT2 ? (float*)g_x2 : yg;
    const unsigned long long* wbh =
        CONV == 0 ? g_wbh0 : (CONV == 1 ? g_wbh1 : g_wbh2);
    const unsigned long long* wbl =
        CONV == 0 ? g_wbl0 : (CONV == 1 ? g_wbl1 : g_wbl2);

    auto stage = [&](int c, int buf) {
        uint32_t aoff = smb + buf * ABLK;
        size_t abase = ((size_t)tile * CHUNKS + c) * 8192;
        #pragma unroll
        for (int i = 0; i < 2; i++) {
            int o = tid + i * 256;
            int r = o >> 2, s = o & 3;
            uint32_t d = aoff + r * 80 + s * 16;
            size_t g = abase + r * 64 + s * 16;
            cpasync16(d, (const char*)g_abh + g);
            cpasync16(d + ABUF, (const char*)g_abl + g);
        }
        uint32_t boff = smb + 2 * ABLK + buf * (2 * BB);
        #pragma unroll
        for (int i = 0; i < BSEG / 256; i++) {
            int o = tid + i * 256;
            int r = o / (OUTD / 8), s = o % (OUTD / 8);
            size_t g = ((size_t)(c * 32 + r) * OUTD + s * 8) * 2;
            uint32_t d = boff + (r * BST + s * 8) * 2;
            cpasync16(d, (const char*)wbh + g);
            cpasync16(d + BB, (const char*)wbl + g);
        }
    };

    float acc[NT][4] = {};

    stage(0, 0);
    cp_commit();
    for (int c = 0; c < CHUNKS; c++) {
        if (c + 1 < CHUNKS) {
            stage(c + 1, (c + 1) & 1);
            cp_commit();
            cp_wait<1>();
        } else {
            cp_wait<0>();
        }
        __syncthreads();
        int buf = c & 1;
        uint32_t aoff = smb + buf * ABLK;
        uint32_t boff = smb + 2 * ABLK + buf * (2 * BB);
        #pragma unroll
        for (int kk = 0; kk < 32; kk += 16) {
            uint32_t ah[4], al[4];
            uint32_t ad = aoff
                + ((mp * 32 + (lane & 15) + ((lane >> 4) ? 0 : 0)) * 0);
            // A fragment: rows mp*32.. — two 16-row ldms per kk step
            #pragma unroll
            for (int m = 0; m < 1; m++) {}
            // (addresses computed inline below)
            uint32_t ad0 = aoff
                + ((mp * 32 + 0 * 16 + (lane & 15)) * AST
                   + kk + (lane >> 4) * 8) * 2;
            uint32_t ad1 = aoff
                + ((mp * 32 + 1 * 16 + (lane & 15)) * AST
                   + kk + (lane >> 4) * 8) * 2;
            uint32_t ah0[4], al0[4], ah1[4], al1[4];
            ldmA(ah0, ad0);
            ldmA(al0, ad0 + ABUF);
            ldmA(ah1, ad1);
            ldmA(al1, ad1 + ABUF);
            uint32_t bh[2 * NT], bl[2 * NT];
            #pragma unroll
            for (int jp = 0; jp < NT / 2; jp++) {
                uint32_t bd = boff
                    + ((kk + (lane & 15)) * BST
                       + nh * NHALF + jp * 16 + (lane >> 4) * 8) * 2;
                ldmBT(bh + jp * 4, bd);
                ldmBT(bl + jp * 4, bd + BB);
            }
            #pragma unroll
            for (int j = 0; j < NT; j++) {
                mma16816(acc[j], ah0, bh + j * 2);
                mma16816(acc[j], al0, bh + j * 2);
                mma16816(acc[j], ah0, bl + j * 2);
            }
            // second 16-row group accumulates into the SAME acc? NO — distinct
            // rows need distinct accumulators. Use acc2.
            (void)ah1; (void)al1; (void)ah; (void)al; (void)ad;
        }
        __syncthreads();
    }
    // NOTE: block handles 128 rows via two 16-row groups per warp — see acc2
    // structure below. (This placeholder path is unreachable; real kernel uses
    // the m-loop version.)
    (void)acc; (void)bias; (void)resid; (void)y; (void)mp; (void)nh;
}

// Real mma_conv (m-loop over 2 row groups, as in the 668us R9 kernel).
template<int OUTD, int MODE, int YOUT2, int CONV>
__global__ void __launch_bounds__(256)
mma_conv2(const float* __restrict__ bias,
          const float* __restrict__ resid,
          float* __restrict__ yg) {
    constexpr int NT = OUTD / 16;
    constexpr int NHALF = OUTD / 2;
    constexpr int BST = OUTD + 8;
    constexpr int BB  = 32 * BST * 2;
    constexpr int BSEG = 32 * OUTD / 8;
    extern __shared__ char smdyn[];
    uint32_t smb = smem_u32(smdyn);
    int tid = threadIdx.x, lane = tid & 31, w = tid >> 5;
    int mp = w & 3, nh = w >> 2;
    int tile = blockIdx.x;
    float* y = YOUT2 ? (float*)g_x2 : yg;
    const unsigned long long* wbh =
        CONV == 0 ? g_wbh0 : (CONV == 1 ? g_wbh1 : g_wbh2);
    const unsigned long long* wbl =
        CONV == 0 ? g_wbl0 : (CONV == 1 ? g_wbl1 : g_wbl2);

    auto stage = [&](int c, int buf) {
        uint32_t aoff = smb + buf * ABLK;
        size_t abase = ((size_t)tile * CHUNKS + c) * 8192;
        #pragma unroll
        for (int i = 0; i < 2; i++) {
            int o = tid + i * 256;
            int r = o >> 2, s = o & 3;
            uint32_t d = aoff + r * 80 + s * 16;
            size_t g = abase + r * 64 + s * 16;
            cpasync16(d, (const char*)g_abh + g);
            cpasync16(d + ABUF, (const char*)g_abl + g);
        }
        uint32_t boff = smb + 2 * ABLK + buf * (2 * BB);
        #pragma unroll
        for (int i = 0; i < BSEG / 256; i++) {
            int o = tid + i * 256;
            int r = o / (OUTD / 8), s = o % (OUTD / 8);
            size_t g = ((size_t)(c * 32 + r) * OUTD + s * 8) * 2;
            uint32_t d = boff + (r * BST + s * 8) * 2;
            cpasync16(d, (const char*)wbh + g);
            cpasync16(d + BB, (const char*)wbl + g);
        }
    };

    float acc[2][NT][4] = {};

    stage(0, 0);
    cp_commit();
    for (int c = 0; c < CHUNKS; c++) {
        if (c + 1 < CHUNKS) {
            stage(c + 1, (c + 1) & 1);
            cp_commit();
            cp_wait<1>();
        } else {
            cp_wait<0>();
        }
        __syncthreads();
        int buf = c & 1;
        uint32_t aoff = smb + buf * ABLK;
        uint32_t boff = smb + 2 * ABLK + buf * (2 * BB);
        #pragma unroll
        for (int kk = 0; kk < 32; kk += 16) {
            uint32_t ah[2][4], al[2][4];
            #pragma unroll
            for (int m = 0; m < 2; m++) {
                uint32_t ad = aoff
                    + ((mp * 32 + m * 16 + (lane & 15)) * AST
                       + kk + (lane >> 4) * 8) * 2;
                ldmA(ah[m], ad);
                ldmA(al[m], ad + ABUF);
            }
            uint32_t bh[2 * NT], bl[2 * NT];
            #pragma unroll
            for (int jp = 0; jp < NT / 2; jp++) {
                uint32_t bd = boff
                    + ((kk + (lane & 15)) * BST
                       + nh * NHALF + jp * 16 + (lane >> 4) * 8) * 2;
                ldmBT(bh + jp * 4, bd);
                ldmBT(bl + jp * 4, bd + BB);
            }
            #pragma unroll
            for (int m = 0; m < 2; m++)
                #pragma unroll
                for (int j = 0; j < NT; j++) {
                    mma16816(acc[m][j], ah[m], bh + j * 2);
                    mma16816(acc[m][j], al[m], bh + j * 2);
                    mma16816(acc[m][j], ah[m], bl + j * 2);
                }
        }
        __syncthreads();
    }

    #pragma unroll
    for (int m = 0; m < 2; m++) {
        int r0 = tile * 128 + mp * 32 + m * 16 + (lane >> 2);
        int r1 = r0 + 8;
        #pragma unroll
        for (int j = 0; j < NT; j++) {
            int col = nh * NHALF + j * 8 + (lane & 3) * 2;
            float2 bb = *(const float2*)(bias + col);
            float2 v0 = make_float2(acc[m][j][0] + bb.x, acc[m][j][1] + bb.y);
            float2 v1 = make_float2(acc[m][j][2] + bb.x, acc[m][j][3] + bb.y);
            if (MODE == 0) {
                v0.x = fmaxf(v0.x, 0.f); v0.y = fmaxf(v0.y, 0.f);
                v1.x = fmaxf(v1.x, 0.f); v1.y = fmaxf(v1.y, 0.f);
            } else if (MODE == 1) {
                if (r0 < NNODES) {
                    float2 rr = *(const float2*)(resid + (size_t)r0 * OUTD + col);
                    v0.x = fmaxf(v0.x, 0.f) + rr.x;
                    v0.y = fmaxf(v0.y, 0.f) + rr.y;
                }
                if (r1 < NNODES) {
                    float2 rr = *(const float2*)(resid + (size_t)r1 * OUTD + col);
                    v1.x = fmaxf(v1.x, 0.f) + rr.x;
                    v1.y = fmaxf(v1.y, 0.f) + rr.y;
                }
            }
            if (r0 < NNODES) *(float2*)(y + (size_t)r0 * OUTD + col) = v0;
            if (r1 < NNODES) *(float2*)(y + (size_t)r1 * OUTD + col) = v1;
        }
    }
}

// ---------------- launch ----------------------------------------------------
extern "C" void kernel_launch(void* const* d_in, const int* in_sizes, int n_in,
                              void* d_out, int out_size) {
    const float* x_paper  = (const float*)d_in[0];
    const float* x_author = (const float*)d_in[1];
    const float* W_paper  = (const float*)d_in[2];
    const float* b_paper  = (const float*)d_in[3];
    const float* W_author = (const float*)d_in[4];
    const float* b_author = (const float*)d_in[5];
    const float* bases0 = (const float*)d_in[6];
    const float* comp0  = (const float*)d_in[7];
    const float* root0  = (const float*)d_in[8];
    const float* bias0  = (const float*)d_in[9];
    const float* bases1 = (const float*)d_in[10];
    const float* comp1  = (const float*)d_in[11];
    const float* root1  = (const float*)d_in[12];
    const float* bias1  = (const float*)d_in[13];
    const float* bases2 = (const float*)d_in[14];
    const float* comp2  = (const float*)d_in[15];
    const float* root2  = (const float*)d_in[16];
    const float* bias2  = (const float*)d_in[17];
    const void*  edge_index = d_in[18];
    const void*  edge_type  = d_in[19];

    // output pytree flat order: out [N,64], x_init, x_init, h0 (each [N,128])
    float* out0 = (float*)d_out;
    float* lat0 = out0 + (size_t)NNODES * OUTD2;
    float* lat1 = lat0 + (size_t)NNODES * HID;
    float* lat2 = lat1 + (size_t)NNODES * HID;

    const int T = 256;
    const int gpre  = (NSEG + NNODES + T - 1) / T;
    const int gedge = (NEDGE + T - 1) / T;
    const int gagg  = NTILE * 4;                  // 1564 blocks x 32 rows

    const int smemP = APTOT + 4 * (32 * (HID + 8) * 2);     // 100352
    const int smemA = 2 * ABLK + 4 * 32 * (HID + 8) * 2;    // 75776
    const int smemB = 2 * ABLK + 4 * 32 * (OUTD2 + 8) * 2;  // 59392

    cudaFuncSetAttribute(proj_conv,
                         cudaFuncAttributeMaxDynamicSharedMemorySize, smemP);
    cudaFuncSetAttribute(mma_conv2<HID,   0, 0, 0>,
                         cudaFuncAttributeMaxDynamicSharedMemorySize, smemA);
    cudaFuncSetAttribute(mma_conv2<HID,   1, 1, 1>,
                         cudaFuncAttributeMaxDynamicSharedMemorySize, smemA);
    cudaFuncSetAttribute(mma_conv2<OUTD2, 2, 0, 2>,
                         cudaFuncAttributeMaxDynamicSharedMemorySize, smemB);

    // 1: zero + dtype + all weight prep
    pre_kernel<<<gpre, T>>>((const int*)edge_index,
                            bases0, root0, bases1, root1, bases2, root2,
                            W_paper, W_author);
    // 2: padded-slot scatter + rel counts
    fill_kernel<<<gedge, T>>>(edge_index, edge_type);
    // 3: HMMA projections -> x_init into both latent slots
    proj_conv<<<2 * NPB, T, smemP>>>(x_paper, x_author, b_paper, b_author,
                                     lat0, lat1);

    // 4: conv0 aggregation  [ncu captures 4th launch]
    agg_kernel<0><<<gagg, T>>>(lat0, comp0);
    // 5: conv0 GEMM -> h0 = relu(.) -> lat2
    mma_conv2<HID, 0, 0, 0><<<NTILE, T, smemA>>>(bias0, nullptr, lat2);

    // 6-7: conv1: x = h0 -> x2 = h0 + relu(.) -> g_x2
    agg_kernel<0><<<gagg, T>>>(lat2, comp1);
    mma_conv2<HID, 1, 1, 1><<<NTILE, T, smemA>>>(bias1, lat2, nullptr);

    // 8-9: conv2: x = g_x2 -> out (no relu) -> out0
    agg_kernel<1><<<gagg, T>>>(nullptr, comp2);
    mma_conv2<OUTD2, 2, 0, 2><<<NTILE, T, smemB>>>(bias2, nullptr, out0);
}

// round 14
// speedup vs baseline: 1.8119x; 1.0192x over previous
#include <cuda_runtime.h>
#include <cuda_bf16.h>
#include <cstddef>
#include <cstdint>

#define NNODES 50000
#define NPER   25000
#define NEDGE  600000
#define RREL   8
#define NB     4
#define INDIM  256
#define HID    128
#define OUTD2  64
#define NSEG   (NNODES * RREL)   // 400000
#define NTILE  391               // ceil(50000/128)
#define MAXD   96                // padded slots per dst
#define CHUNKS 20                // 640 / 32
#define AST    40                // A smem row stride in mma_conv (bf16)
#define ABUF   10240             // 128*40*2 bytes, one A hi or lo buffer
#define ABLK   20480             // per double-buffer step (hi+lo)
#define NPB    391               // proj blocks per node type (ceil 25000/64)
#define PCH    8                 // proj K chunks (256/32)
#define APTOT  (PCH * 2 * 4096)  // proj A smem: 65536

// ---------------- low-level helpers -----------------------------------------
__device__ __forceinline__ uint32_t smem_u32(const void* p) {
    uint32_t a;
    asm("{ .reg .u64 t; cvta.to.shared.u64 t, %1; cvt.u32.u64 %0, t; }"
        : "=r"(a) : "l"(p));
    return a;
}
__device__ __forceinline__ void cpasync16(uint32_t sdst, const void* gsrc) {
    asm volatile("{ .reg .u64 g; cvta.to.global.u64 g, %1;"
                 " cp.async.cg.shared.global [%0], [g], 16; }"
                 :: "r"(sdst), "l"(gsrc) : "memory");
}
__device__ __forceinline__ void cp_commit() {
    asm volatile("cp.async.commit_group;" ::: "memory");
}
template<int N>
__device__ __forceinline__ void cp_wait() {
    asm volatile("cp.async.wait_group %0;" :: "n"(N) : "memory");
}
__device__ __forceinline__ void ldmA(uint32_t* r, uint32_t addr) {
    asm volatile("ldmatrix.sync.aligned.m8n8.x4.shared.b16 {%0,%1,%2,%3}, [%4];"
        : "=r"(r[0]), "=r"(r[1]), "=r"(r[2]), "=r"(r[3]) : "r"(addr));
}
__device__ __forceinline__ void ldmBT(uint32_t* r, uint32_t addr) {
    asm volatile("ldmatrix.sync.aligned.m8n8.x4.trans.shared.b16 {%0,%1,%2,%3}, [%4];"
        : "=r"(r[0]), "=r"(r[1]), "=r"(r[2]), "=r"(r[3]) : "r"(addr));
}
__device__ __forceinline__ void mma16816(float* d, const uint32_t* a,
                                         const uint32_t* b) {
    asm volatile(
        "mma.sync.aligned.m16n8k16.row.col.f32.bf16.bf16.f32 "
        "{%0,%1,%2,%3}, {%4,%5,%6,%7}, {%8,%9}, {%0,%1,%2,%3};"
        : "+f"(d[0]), "+f"(d[1]), "+f"(d[2]), "+f"(d[3])
        : "r"(a[0]), "r"(a[1]), "r"(a[2]), "r"(a[3]), "r"(b[0]), "r"(b[1]));
}

// Compact A-tile swizzle (validated in R12/R13 runs).
__device__ __forceinline__ uint32_t aphys(int m, int s) {
    return (uint32_t)(m * 64 + (s ^ (((m >> 1) & 3) << 4)));
}

// ---------------- fast bf16 hi/lo split (cvt.rn.bf16x2) ----------------------
__device__ __forceinline__ uint32_t pack2(float lo, float hi) {
    uint32_t r;
    asm("cvt.rn.bf16x2.f32 %0, %1, %2;" : "=r"(r) : "f"(hi), "f"(lo));
    return r;
}
__device__ __forceinline__ void split4f(float4 v, uint32_t& h0, uint32_t& h1,
                                        uint32_t& l0, uint32_t& l1) {
    h0 = pack2(v.x, v.y);
    h1 = pack2(v.z, v.w);
    float hx = __uint_as_float(h0 << 16);
    float hy = __uint_as_float(h0 & 0xffff0000u);
    float hz = __uint_as_float(h1 << 16);
    float hw = __uint_as_float(h1 & 0xffff0000u);
    l0 = pack2(v.x - hx, v.y - hy);
    l1 = pack2(v.z - hz, v.w - hw);
}
__device__ __forceinline__ void split4u(float4 v, unsigned long long& H,
                                        unsigned long long& L) {
    uint32_t h0, h1, l0, l1;
    split4f(v, h0, h1, l0, l1);
    H = (unsigned long long)h0 | ((unsigned long long)h1 << 32);
    L = (unsigned long long)l0 | ((unsigned long long)l1 << 32);
}

// ---------------- scratch (device globals: no allocation allowed) ----------
__device__ int   g_cnt[NSEG];
__device__ int   g_fill[NNODES];
__device__ int   g_eslots[(size_t)NNODES * MAXD];
__device__ float g_x2[(size_t)NNODES * HID];
__device__ int   g_is64;
// aggregated A bf16 hi/lo in MMA chunk layout: [tile][chunk(20)][row(128)][k(32)]
__device__ unsigned long long g_abh[(size_t)NTILE * CHUNKS * 1024];
__device__ unsigned long long g_abl[(size_t)NTILE * CHUNKS * 1024];
// stacked conv weights [k=640][outd] bf16 hi/lo
__device__ unsigned long long g_wbh0[20480], g_wbl0[20480];
__device__ unsigned long long g_wbh1[20480], g_wbl1[20480];
__device__ unsigned long long g_wbh2[10240], g_wbl2[10240];
// proj weights [k=256][128] bf16 hi/lo, per node type
__device__ unsigned long long g_wpph[8192], g_wppl[8192];
__device__ unsigned long long g_wpah[8192], g_wpal[8192];

__device__ __forceinline__ int ld_idx(const void* p, long i) {
    return g_is64 ? (int)((const long long*)p)[i] : ((const int*)p)[i];
}

// ---------------- launch 1: zero + dtype detect + all weight prep -----------
__global__ void pre_kernel(const int* p,
                           const float* b0, const float* r0,
                           const float* b1, const float* r1,
                           const float* b2, const float* r2,
                           const float* Wp, const float* Wa) {
    int i = blockIdx.x * blockDim.x + threadIdx.x;
    if (i == 0) {
        int any = 0;
        #pragma unroll 8
        for (int j = 1; j < 2048; j += 2) any |= p[j];
        g_is64 = (any == 0) ? 1 : 0;
    }
    if (i < NSEG) g_cnt[i] = 0;
    else if (i < NSEG + NNODES) g_fill[i - NSEG] = 0;

    if (i < 51200) {   // conv weights: 4 bf16 hi/lo values per thread
        int conv = i < 20480 ? 0 : (i < 40960 ? 1 : 2);
        int u = i - (conv == 1 ? 20480 : (conv == 2 ? 40960 : 0));
        int outd = (conv == 2) ? OUTD2 : HID;
        const float* bases = conv == 0 ? b0 : (conv == 1 ? b1 : b2);
        const float* root  = conv == 0 ? r0 : (conv == 1 ? r1 : r2);
        unsigned long long* oh = conv == 0 ? g_wbh0 : (conv == 1 ? g_wbh1 : g_wbh2);
        unsigned long long* ol = conv == 0 ? g_wbl0 : (conv == 1 ? g_wbl1 : g_wbl2);
        int base = u * 4;
        int k = base / outd, o0 = base % outd;
        float4 v;
        float* vv = (float*)&v;
        #pragma unroll
        for (int j = 0; j < 4; j++)
            vv[j] = (k < 512) ? bases[(size_t)k * outd + o0 + j]
                              : root[(size_t)(k - 512) * outd + o0 + j];
        unsigned long long H, L;
        split4u(v, H, L);
        oh[u] = H; ol[u] = L;
    } else if (i < 67584) {  // proj weights
        int u = i - 51200;
        int typ = u >= 8192;
        int uu = u & 8191;
        const float* W = typ ? Wa : Wp;
        unsigned long long* oh = typ ? g_wpah : g_wpph;
        unsigned long long* ol = typ ? g_wpal : g_wppl;
        float4 v = *(const float4*)(W + (size_t)uu * 4);
        unsigned long long H, L;
        split4u(v, H, L);
        oh[uu] = H; ol[uu] = L;
    }
}

// ---------------- launch 2: scatter edges into padded slots + rel counts ----
__global__ void fill_kernel(const void* ei, const void* et) {
    int e = blockIdx.x * blockDim.x + threadIdx.x;
    if (e >= NEDGE) return;
    int src = ld_idx(ei, e);
    int dst = ld_idx(ei, (long)NEDGE + e);
    int t   = ld_idx(et, e);
    int pos = atomicAdd(&g_fill[dst], 1);
    if (pos < MAXD) g_eslots[(size_t)dst * MAXD + pos] = src * RREL + t;
    atomicAdd(&g_cnt[dst * RREL + t], 1);
}

// ---------------- launch 3: HMMA input projection (both node types) ---------
__global__ void __launch_bounds__(256)
proj_conv(const float* __restrict__ xp, const float* __restrict__ xa,
          const float* __restrict__ bp, const float* __restrict__ ba,
          float* __restrict__ o1, float* __restrict__ o2) {
    constexpr int OUTD = HID;
    constexpr int NT = 8, NHALF = 64;
    constexpr int BST = OUTD + 8;
    constexpr int BHB = 32 * BST * 2;
    constexpr int B_OFF = APTOT;
    extern __shared__ char sm[];
    uint32_t smb = smem_u32(sm);
    int tid = threadIdx.x, lane = tid & 31, w = tid >> 5;
    int half = blockIdx.x >= NPB;
    int blk = blockIdx.x - (half ? NPB : 0);
    int n0 = blk * 64;
    const float* x = half ? xa : xp;
    const float* bias = half ? ba : bp;
    const unsigned long long* wbh = half ? g_wpah : g_wpph;
    const unsigned long long* wbl = half ? g_wpal : g_wppl;

    auto stageB = [&](int c, int buf) {
        uint32_t boff = smb + B_OFF + buf * (2 * BHB);
        #pragma unroll
        for (int i = 0; i < 2; i++) {
            int o = tid + i * 256;           // 512 16B segs
            int r = o >> 4, s = o & 15;
            size_t g = ((size_t)(c * 32 + r) * OUTD + s * 8) * 2;
            uint32_t d = boff + (r * BST + s * 8) * 2;
            cpasync16(d, (const char*)wbh + g);
            cpasync16(d + BHB, (const char*)wbl + g);
        }
    };
    stageB(0, 0);
    cp_commit();

    // phase 1: convert x rows into smem hi/lo chunk tiles
    #pragma unroll
    for (int i = 0; i < 8; i++) {
        int m = w * 8 + i;
        int n = n0 + m;
        bool ok = n < NPER;
        #pragma unroll
        for (int h = 0; h < 2; h++) {
            float4 v = make_float4(0.f, 0.f, 0.f, 0.f);
            if (ok) v = *(const float4*)(x + (size_t)n * INDIM + h * 128 + lane * 4);
            uint32_t h0, h1, l0, l1;
            split4f(v, h0, h1, l0, l1);
            int c = h * 4 + (lane >> 3);
            uint32_t ph = aphys(m, (lane & 7) * 8);
            *(uint2*)(sm + (uint32_t)(c * 2 + 0) * 4096 + ph) = make_uint2(h0, h1);
            *(uint2*)(sm + (uint32_t)(c * 2 + 1) * 4096 + ph) = make_uint2(l0, l1);
        }
    }
    __syncthreads();

    // phase 2: 8-chunk HMMA mainloop
    int mp = w & 3, nh = w >> 2;
    float acc[NT][4] = {};
    for (int c = 0; c < PCH; c++) {
        if (c + 1 < PCH) {
            stageB(c + 1, (c + 1) & 1);
            cp_commit();
            cp_wait<1>();
        } else {
            cp_wait<0>();
        }
        __syncthreads();
        uint32_t ahi = smb + (uint32_t)(c * 2 + 0) * 4096;
        uint32_t alo = smb + (uint32_t)(c * 2 + 1) * 4096;
        uint32_t boff = smb + B_OFF + (c & 1) * (2 * BHB);
        #pragma unroll
        for (int kk = 0; kk < 32; kk += 16) {
            int am = mp * 16 + (lane & 15);
            uint32_t ad = aphys(am, kk * 2 + (lane >> 4) * 16);
            uint32_t ah[4], al[4];
            ldmA(ah, ahi + ad);
            ldmA(al, alo + ad);
            uint32_t bh[2 * NT], bl[2 * NT];
            #pragma unroll
            for (int jp = 0; jp < NT / 2; jp++) {
                uint32_t bd = boff
                    + ((kk + (lane & 15)) * BST
                       + nh * NHALF + jp * 16 + (lane >> 4) * 8) * 2;
                ldmBT(bh + jp * 4, bd);
                ldmBT(bl + jp * 4, bd + BHB);
            }
            #pragma unroll
            for (int j = 0; j < NT; j++) {
                mma16816(acc[j], ah, bh + j * 2);
                mma16816(acc[j], al, bh + j * 2);
                mma16816(acc[j], ah, bl + j * 2);
            }
        }
        __syncthreads();
    }

    // epilogue: relu(acc + bias) -> both latent slots
    int r0 = n0 + mp * 16 + (lane >> 2);
    int r1 = r0 + 8;
    size_t gb = (size_t)(half ? NPER : 0) * HID;
    #pragma unroll
    for (int j = 0; j < NT; j++) {
        int col = nh * NHALF + j * 8 + (lane & 3) * 2;
        float2 bb = *(const float2*)(bias + col);
        float2 v0 = make_float2(fmaxf(acc[j][0] + bb.x, 0.f),
                                fmaxf(acc[j][1] + bb.y, 0.f));
        float2 v1 = make_float2(fmaxf(acc[j][2] + bb.x, 0.f),
                                fmaxf(acc[j][3] + bb.y, 0.f));
        if (r0 < NPER) {
            *(float2*)(o1 + gb + (size_t)r0 * HID + col) = v0;
            *(float2*)(o2 + gb + (size_t)r0 * HID + col) = v0;
        }
        if (r1 < NPER) {
            *(float2*)(o1 + gb + (size_t)r1 * HID + col) = v1;
            *(float2*)(o2 + gb + (size_t)r1 * HID + col) = v1;
        }
    }
}

// ---------------- agg: slot gather -> bf16 hi/lo A in chunk layout ----------
// Per block 32 dst rows, 8 warps x 4 rows (2 chains x 2 iterations).
// Per-(row,rel) coefficient float4 table (nrm*comp) precomputed in smem;
// entry 256 is zero for inactive chains.
template<int XIN2>
__global__ void __launch_bounds__(256, 4)
agg_kernel(const float* __restrict__ xg, const float* __restrict__ comp) {
    __shared__ __align__(16) float4 coef_s[260];
    const float* x = XIN2 ? (const float*)g_x2 : xg;
    int tid = threadIdx.x;
    int n0 = blockIdx.x * 32;
    {
        int n = n0 + (tid >> 3);
        int r = tid & 7;
        float c = (n < NNODES) ? (float)g_cnt[n * RREL + r] : 1.0f;
        float nv = 1.0f / fmaxf(c, 1.0f);
        float4 cf;
        cf.x = nv * comp[r * 4 + 0];
        cf.y = nv * comp[r * 4 + 1];
        cf.z = nv * comp[r * 4 + 2];
        cf.w = nv * comp[r * 4 + 3];
        coef_s[tid] = cf;
        if (tid == 0) coef_s[256] = make_float4(0.f, 0.f, 0.f, 0.f);
    }
    __syncthreads();

    int lane = tid & 31, w = tid >> 5;
    auto aidx = [&](int n, int p) -> size_t {
        int c = p * 4 + (lane >> 3);
        return ((size_t)(n >> 7) * CHUNKS + c) * 1024 + (n & 127) * 8 + (lane & 7);
    };
    #pragma unroll
    for (int pp = 0; pp < 2; pp++) {
        int mA = w * 4 + pp * 2, mB = mA + 1;
        int nA = n0 + mA, nB = n0 + mB;
        float4 z4 = make_float4(0.f, 0.f, 0.f, 0.f);
        {
            float4 xav = (nA < NNODES)
                ? *(const float4*)(x + (size_t)nA * HID + lane * 4) : z4;
            float4 xbv = (nB < NNODES)
                ? *(const float4*)(x + (size_t)nB * HID + lane * 4) : z4;
            unsigned long long H, L;
            split4u(xav, H, L); g_abh[aidx(nA, 4)] = H; g_abl[aidx(nA, 4)] = L;
            split4u(xbv, H, L); g_abh[aidx(nB, 4)] = H; g_abl[aidx(nB, 4)] = L;
        }
        int endA = 0, endB = 0;
        size_t sA = (size_t)nA * MAXD, sB = (size_t)nB * MAXD;
        if (nA < NNODES) endA = min(g_fill[nA], MAXD);
        if (nB < NNODES) endB = min(g_fill[nB], MAXD);

        float4 aA[4] = {z4, z4, z4, z4};
        float4 aB[4] = {z4, z4, z4, z4};
        int eA = 0, eB = 0;
        int cA = (eA < endA) ? g_eslots[sA] : 0;
        int cB = (eB < endB) ? g_eslots[sB] : 0;
        while (eA < endA || eB < endB) {
            bool dA = eA < endA, dB = eB < endB;
            float4 vA = *((const float4*)(x + (size_t)(cA >> 3) * HID) + lane);
            float4 vB = *((const float4*)(x + (size_t)(cB >> 3) * HID) + lane);
            int cA2 = (eA + 1 < endA) ? g_eslots[sA + eA + 1] : 0;
            int cB2 = (eB + 1 < endB) ? g_eslots[sB + eB + 1] : 0;
            float4 cfA = coef_s[dA ? ((mA << 3) | (cA & 7)) : 256];
            float4 cfB = coef_s[dB ? ((mB << 3) | (cB & 7)) : 256];
            aA[0].x = fmaf(cfA.x, vA.x, aA[0].x);
            aA[0].y = fmaf(cfA.x, vA.y, aA[0].y);
            aA[0].z = fmaf(cfA.x, vA.z, aA[0].z);
            aA[0].w = fmaf(cfA.x, vA.w, aA[0].w);
            aA[1].x = fmaf(cfA.y, vA.x, aA[1].x);
            aA[1].y = fmaf(cfA.y, vA.y, aA[1].y);
            aA[1].z = fmaf(cfA.y, vA.z, aA[1].z);
            aA[1].w = fmaf(cfA.y, vA.w, aA[1].w);
            aA[2].x = fmaf(cfA.z, vA.x, aA[2].x);
            aA[2].y = fmaf(cfA.z, vA.y, aA[2].y);
            aA[2].z = fmaf(cfA.z, vA.z, aA[2].z);
            aA[2].w = fmaf(cfA.z, vA.w, aA[2].w);
            aA[3].x = fmaf(cfA.w, vA.x, aA[3].x);
            aA[3].y = fmaf(cfA.w, vA.y, aA[3].y);
            aA[3].z = fmaf(cfA.w, vA.z, aA[3].z);
            aA[3].w = fmaf(cfA.w, vA.w, aA[3].w);
            aB[0].x = fmaf(cfB.x, vB.x, aB[0].x);
            aB[0].y = fmaf(cfB.x, vB.y, aB[0].y);
            aB[0].z = fmaf(cfB.x, vB.z, aB[0].z);
            aB[0].w = fmaf(cfB.x, vB.w, aB[0].w);
            aB[1].x = fmaf(cfB.y, vB.x, aB[1].x);
            aB[1].y = fmaf(cfB.y, vB.y, aB[1].y);
            aB[1].z = fmaf(cfB.y, vB.z, aB[1].z);
            aB[1].w = fmaf(cfB.y, vB.w, aB[1].w);
            aB[2].x = fmaf(cfB.z, vB.x, aB[2].x);
            aB[2].y = fmaf(cfB.z, vB.y, aB[2].y);
            aB[2].z = fmaf(cfB.z, vB.z, aB[2].z);
            aB[2].w = fmaf(cfB.z, vB.w, aB[2].w);
            aB[3].x = fmaf(cfB.w, vB.x, aB[3].x);
            aB[3].y = fmaf(cfB.w, vB.y, aB[3].y);
            aB[3].z = fmaf(cfB.w, vB.z, aB[3].z);
            aB[3].w = fmaf(cfB.w, vB.w, aB[3].w);
            eA += dA; eB += dB;
            if (dA) cA = cA2;
            if (dB) cB = cB2;
        }
        #pragma unroll
        for (int b = 0; b < 4; b++) {
            unsigned long long H, L;
            split4u(aA[b], H, L); g_abh[aidx(nA, b)] = H; g_abl[aidx(nA, b)] = L;
            split4u(aB[b], H, L); g_abh[aidx(nB, b)] = H; g_abl[aidx(nB, b)] = L;
        }
    }
}

// ---------------- HMMA conv: D = Ah@Bh + Al@Bh + Ah@Bl ----------------------
// Per block: 128 rows x OUTD. K=640 in 20 chunks of 32, cp.async double-buffer,
// 2 blocks/SM. Weights selected by CONV inside device code.
template<int OUTD, int MODE, int YOUT2, int CONV>
__global__ void __launch_bounds__(256)
mma_conv(const float* __restrict__ bias,
         const float* __restrict__ resid,
         float* __restrict__ yg) {
    constexpr int NT = OUTD / 16;
    constexpr int NHALF = OUTD / 2;
    constexpr int BST = OUTD + 8;
    constexpr int BB  = 32 * BST * 2;
    constexpr int BSEG = 32 * OUTD / 8;
    extern __shared__ char smdyn[];
    uint32_t smb = smem_u32(smdyn);
    int tid = threadIdx.x, lane = tid & 31, w = tid >> 5;
    int mp = w & 3, nh = w >> 2;
    int tile = blockIdx.x;
    float* y = YOUT2 ? (float*)g_x2 : yg;
    const unsigned long long* wbh =
        CONV == 0 ? g_wbh0 : (CONV == 1 ? g_wbh1 : g_wbh2);
    const unsigned long long* wbl =
        CONV == 0 ? g_wbl0 : (CONV == 1 ? g_wbl1 : g_wbl2);

    auto stage = [&](int c, int buf) {
        uint32_t aoff = smb + buf * ABLK;
        size_t abase = ((size_t)tile * CHUNKS + c) * 8192;
        #pragma unroll
        for (int i = 0; i < 2; i++) {
            int o = tid + i * 256;
            int r = o >> 2, s = o & 3;
            uint32_t d = aoff + r * 80 + s * 16;
            size_t g = abase + r * 64 + s * 16;
            cpasync16(d, (const char*)g_abh + g);
            cpasync16(d + ABUF, (const char*)g_abl + g);
        }
        uint32_t boff = smb + 2 * ABLK + buf * (2 * BB);
        #pragma unroll
        for (int i = 0; i < BSEG / 256; i++) {
            int o = tid + i * 256;
            int r = o / (OUTD / 8), s = o % (OUTD / 8);
            size_t g = ((size_t)(c * 32 + r) * OUTD + s * 8) * 2;
            uint32_t d = boff + (r * BST + s * 8) * 2;
            cpasync16(d, (const char*)wbh + g);
            cpasync16(d + BB, (const char*)wbl + g);
        }
    };

    float acc[2][NT][4] = {};

    stage(0, 0);
    cp_commit();
    for (int c = 0; c < CHUNKS; c++) {
        if (c + 1 < CHUNKS) {
            stage(c + 1, (c + 1) & 1);
            cp_commit();
            cp_wait<1>();
        } else {
            cp_wait<0>();
        }
        __syncthreads();
        int buf = c & 1;
        uint32_t aoff = smb + buf * ABLK;
        uint32_t boff = smb + 2 * ABLK + buf * (2 * BB);
        #pragma unroll
        for (int kk = 0; kk < 32; kk += 16) {
            uint32_t ah[2][4], al[2][4];
            #pragma unroll
            for (int m = 0; m < 2; m++) {
                uint32_t ad = aoff
                    + ((mp * 32 + m * 16 + (lane & 15)) * AST
                       + kk + (lane >> 4) * 8) * 2;
                ldmA(ah[m], ad);
                ldmA(al[m], ad + ABUF);
            }
            uint32_t bh[2 * NT], bl[2 * NT];
            #pragma unroll
            for (int jp = 0; jp < NT / 2; jp++) {
                uint32_t bd = boff
                    + ((kk + (lane & 15)) * BST
                       + nh * NHALF + jp * 16 + (lane >> 4) * 8) * 2;
                ldmBT(bh + jp * 4, bd);
                ldmBT(bl + jp * 4, bd + BB);
            }
            #pragma unroll
            for (int m = 0; m < 2; m++)
                #pragma unroll
                for (int j = 0; j < NT; j++) {
                    mma16816(acc[m][j], ah[m], bh + j * 2);
                    mma16816(acc[m][j], al[m], bh + j * 2);
                    mma16816(acc[m][j], ah[m], bl + j * 2);
                }
        }
        __syncthreads();
    }

    #pragma unroll
    for (int m = 0; m < 2; m++) {
        int r0 = tile * 128 + mp * 32 + m * 16 + (lane >> 2);
        int r1 = r0 + 8;
        #pragma unroll
        for (int j = 0; j < NT; j++) {
            int col = nh * NHALF + j * 8 + (lane & 3) * 2;
            float2 bb = *(const float2*)(bias + col);
            float2 v0 = make_float2(acc[m][j][0] + bb.x, acc[m][j][1] + bb.y);
            float2 v1 = make_float2(acc[m][j][2] + bb.x, acc[m][j][3] + bb.y);
            if (MODE == 0) {
                v0.x = fmaxf(v0.x, 0.f); v0.y = fmaxf(v0.y, 0.f);
                v1.x = fmaxf(v1.x, 0.f); v1.y = fmaxf(v1.y, 0.f);
            } else if (MODE == 1) {
                if (r0 < NNODES) {
                    float2 rr = *(const float2*)(resid + (size_t)r0 * OUTD + col);
                    v0.x = fmaxf(v0.x, 0.f) + rr.x;
                    v0.y = fmaxf(v0.y, 0.f) + rr.y;
                }
                if (r1 < NNODES) {
                    float2 rr = *(const float2*)(resid + (size_t)r1 * OUTD + col);
                    v1.x = fmaxf(v1.x, 0.f) + rr.x;
                    v1.y = fmaxf(v1.y, 0.f) + rr.y;
                }
            }
            if (r0 < NNODES) *(float2*)(y + (size_t)r0 * OUTD + col) = v0;
            if (r1 < NNODES) *(float2*)(y + (size_t)r1 * OUTD + col) = v1;
        }
    }
}

// ---------------- launch ----------------------------------------------------
extern "C" void kernel_launch(void* const* d_in, const int* in_sizes, int n_in,
                              void* d_out, int out_size) {
    const float* x_paper  = (const float*)d_in[0];
    const float* x_author = (const float*)d_in[1];
    const float* W_paper  = (const float*)d_in[2];
    const float* b_paper  = (const float*)d_in[3];
    const float* W_author = (const float*)d_in[4];
    const float* b_author = (const float*)d_in[5];
    const float* bases0 = (const float*)d_in[6];
    const float* comp0  = (const float*)d_in[7];
    const float* root0  = (const float*)d_in[8];
    const float* bias0  = (const float*)d_in[9];
    const float* bases1 = (const float*)d_in[10];
    const float* comp1  = (const float*)d_in[11];
    const float* root1  = (const float*)d_in[12];
    const float* bias1  = (const float*)d_in[13];
    const float* bases2 = (const float*)d_in[14];
    const float* comp2  = (const float*)d_in[15];
    const float* root2  = (const float*)d_in[16];
    const float* bias2  = (const float*)d_in[17];
    const void*  edge_index = d_in[18];
    const void*  edge_type  = d_in[19];

    // output pytree flat order: out [N,64], x_init, x_init, h0 (each [N,128])
    float* out0 = (float*)d_out;
    float* lat0 = out0 + (size_t)NNODES * OUTD2;
    float* lat1 = lat0 + (size_t)NNODES * HID;
    float* lat2 = lat1 + (size_t)NNODES * HID;

    const int T = 256;
    const int gpre  = (NSEG + NNODES + T - 1) / T;
    const int gedge = (NEDGE + T - 1) / T;
    const int gagg  = NTILE * 4;                  // 1564 blocks x 32 rows

    const int smemP = APTOT + 4 * (32 * (HID + 8) * 2);     // 100352
    const int smemA = 2 * ABLK + 4 * 32 * (HID + 8) * 2;    // 75776
    const int smemB = 2 * ABLK + 4 * 32 * (OUTD2 + 8) * 2;  // 59392

    cudaFuncSetAttribute(proj_conv,
                         cudaFuncAttributeMaxDynamicSharedMemorySize, smemP);
    cudaFuncSetAttribute(mma_conv<HID,   0, 0, 0>,
                         cudaFuncAttributeMaxDynamicSharedMemorySize, smemA);
    cudaFuncSetAttribute(mma_conv<HID,   1, 1, 1>,
                         cudaFuncAttributeMaxDynamicSharedMemorySize, smemA);
    cudaFuncSetAttribute(mma_conv<OUTD2, 2, 0, 2>,
                         cudaFuncAttributeMaxDynamicSharedMemorySize, smemB);

    // 1: zero + dtype + all weight prep
    pre_kernel<<<gpre, T>>>((const int*)edge_index,
                            bases0, root0, bases1, root1, bases2, root2,
                            W_paper, W_author);
    // 2: padded-slot scatter + rel counts
    fill_kernel<<<gedge, T>>>(edge_index, edge_type);
    // 3: HMMA projections -> x_init into both latent slots
    proj_conv<<<2 * NPB, T, smemP>>>(x_paper, x_author, b_paper, b_author,
                                     lat0, lat1);

    // 4: conv0 aggregation  [ncu captures 4th launch]
    agg_kernel<0><<<gagg, T>>>(lat0, comp0);
    // 5: conv0 GEMM -> h0 = relu(.) -> lat2
    mma_conv<HID, 0, 0, 0><<<NTILE, T, smemA>>>(bias0, nullptr, lat2);

    // 6-7: conv1: x = h0 -> x2 = h0 + relu(.) -> g_x2
    agg_kernel<0><<<gagg, T>>>(lat2, comp1);
    mma_conv<HID, 1, 1, 1><<<NTILE, T, smemA>>>(bias1, lat2, nullptr);

    // 8-9: conv2: x = g_x2 -> out (no relu) -> out0
    agg_kernel<1><<<gagg, T>>>(nullptr, comp2);
    mma_conv<OUTD2, 2, 0, 2><<<NTILE, T, smemB>>>(bias2, nullptr, out0);
}